// round 1
// baseline (speedup 1.0000x reference)
#include <cuda_runtime.h>
#include <stdint.h>

#define NB_COUNT 32
#define DIM 128          // floats per row
#define VEC (DIM / 4)    // 32 float4 per row

// One warp per node. Lane l handles float4 column l (covers all 128 floats).
// The 32 neighbor indices for the node are loaded coalesced (one per lane)
// and broadcast with shfl.
__global__ __launch_bounds__(256) void sum_agg_kernel(
    const int* __restrict__ neighs,
    const float4* __restrict__ emb,   // [num_ids][32] float4
    float4* __restrict__ out,         // [node_count][32] float4
    int node_count)
{
    const int warp = (blockIdx.x * blockDim.x + threadIdx.x) >> 5;
    const int lane = threadIdx.x & 31;
    if (warp >= node_count) return;

    // Coalesced index load: lane l gets neighbor l of this node.
    const int my_idx = neighs[(size_t)warp * NB_COUNT + lane];

    float4 acc0 = make_float4(0.f, 0.f, 0.f, 0.f);
    float4 acc1 = make_float4(0.f, 0.f, 0.f, 0.f);

    // Two halves of 16 to keep many independent loads in flight while
    // bounding register pressure; two accumulators shorten the dep chain.
    #pragma unroll
    for (int j = 0; j < 16; ++j) {
        const int r0 = __shfl_sync(0xffffffffu, my_idx, 2 * j);
        const int r1 = __shfl_sync(0xffffffffu, my_idx, 2 * j + 1);
        const float4 v0 = __ldg(&emb[(size_t)r0 * VEC + lane]);
        const float4 v1 = __ldg(&emb[(size_t)r1 * VEC + lane]);
        acc0.x += v0.x; acc0.y += v0.y; acc0.z += v0.z; acc0.w += v0.w;
        acc1.x += v1.x; acc1.y += v1.y; acc1.z += v1.z; acc1.w += v1.w;
    }

    float4 r;
    r.x = acc0.x + acc1.x;
    r.y = acc0.y + acc1.y;
    r.z = acc0.z + acc1.z;
    r.w = acc0.w + acc1.w;
    out[(size_t)warp * VEC + lane] = r;
}

extern "C" void kernel_launch(void* const* d_in, const int* in_sizes, int n_in,
                              void* d_out, int out_size)
{
    // metadata order: neighs (int32), node_count (int scalar), emb_table (f32)
    const int* neighs = (const int*)d_in[0];
    const float4* emb = (const float4*)d_in[2];
    float4* out = (float4*)d_out;

    const int node_count = out_size / DIM;   // out is [node_count, 128] f32

    const int threads = 256;                  // 8 warps = 8 nodes per block
    const int warps_needed = node_count;
    const int blocks = (warps_needed * 32 + threads - 1) / threads;

    sum_agg_kernel<<<blocks, threads>>>(neighs, emb, out, node_count);
}